// round 3
// baseline (speedup 1.0000x reference)
#include <cuda_runtime.h>

// Problem constants
#define TT 8192      // timesteps
#define FF 64        // layer-0 input features
#define HH 4096      // hidden units per layer
#define PP 4         // projection size (also K for layers 1,2)
#define TB 64        // timesteps per block tile
#define NC 64        // hidden units per block tile
#define NCHUNK (HH / NC)   // 64 hidden chunks

// Scratch (no allocation allowed -> __device__ globals)
__device__ __align__(16) float g_part[TT * NCHUNK * 4];   // 8 MB partial projections
__device__ __align__(16) float g_ybuf[2][TT * 4];         // inter-layer activations

__device__ __forceinline__ float tanh_fast(float x) {
    float y;
    asm("tanh.approx.f32 %0, %1;" : "=f"(y) : "f"(x));
    return y;
}
__device__ __forceinline__ float sig_fast(float x) {
    return 0.5f * tanh_fast(0.5f * x) + 0.5f;
}

__device__ __forceinline__ void dot4(float& acc, const float4 wv, const float4 xv) {
    acc = fmaf(wv.x, xv.x, acc);
    acc = fmaf(wv.y, xv.y, acc);
    acc = fmaf(wv.z, xv.z, acc);
    acc = fmaf(wv.w, xv.w, acc);
}

// Fused: gates GEMM (i,g,o only; f is dead with zero state) + bias +
// LSTM-cell nonlinearity + W_hr projection, emitting per-chunk partials.
// Block tile: TB=64 timesteps x NC=64 hidden. Thread: 2 hidden x 8 timesteps.
template <int K>
__global__ __launch_bounds__(256)
void gate_gemm(const float* __restrict__ Xext, int xsel,
               const float* __restrict__ Wih,
               const float* __restrict__ bih,
               const float* __restrict__ bhh,
               const float* __restrict__ Whr)
{
    const float* __restrict__ X = (xsel < 0) ? Xext : g_ybuf[xsel];

    __shared__ float xs[TB * K];

    const int t0     = blockIdx.x * TB;
    const int nchunk = blockIdx.y;
    const int n0     = nchunk * NC;
    const int tid    = threadIdx.x;

    // Coalesced vector load of the x tile
    for (int i = tid; i < TB * K / 4; i += 256)
        ((float4*)xs)[i] = ((const float4*)(X + t0 * K))[i];
    __syncthreads();

    const int nt = tid & 31;   // hidden lane (0..31)
    const int tt = tid >> 5;   // warp id = timestep subgroup (0..7)
    const int nA = n0 + nt;
    const int nB = n0 + nt + 32;

    const float* wAi = Wih + (size_t)(0 * HH + nA) * K;
    const float* wAg = Wih + (size_t)(2 * HH + nA) * K;
    const float* wAo = Wih + (size_t)(3 * HH + nA) * K;
    const float* wBi = Wih + (size_t)(0 * HH + nB) * K;
    const float* wBg = Wih + (size_t)(2 * HH + nB) * K;
    const float* wBo = Wih + (size_t)(3 * HH + nB) * K;

    float aAi[8] = {}, aAg[8] = {}, aAo[8] = {};
    float aBi[8] = {}, aBg[8] = {}, aBo[8] = {};

#pragma unroll 2
    for (int k = 0; k < K; k += 4) {
        const float4 vAi = *(const float4*)(wAi + k);
        const float4 vAg = *(const float4*)(wAg + k);
        const float4 vAo = *(const float4*)(wAo + k);
        const float4 vBi = *(const float4*)(wBi + k);
        const float4 vBg = *(const float4*)(wBg + k);
        const float4 vBo = *(const float4*)(wBo + k);
#pragma unroll
        for (int t = 0; t < 8; t++) {
            const float4 x4 = *(const float4*)&xs[(tt * 8 + t) * K + k];
            dot4(aAi[t], vAi, x4);
            dot4(aAg[t], vAg, x4);
            dot4(aAo[t], vAo, x4);
            dot4(aBi[t], vBi, x4);
            dot4(aBg[t], vBg, x4);
            dot4(aBo[t], vBo, x4);
        }
    }

    const float bAi = bih[0 * HH + nA] + bhh[0 * HH + nA];
    const float bAg = bih[2 * HH + nA] + bhh[2 * HH + nA];
    const float bAo = bih[3 * HH + nA] + bhh[3 * HH + nA];
    const float bBi = bih[0 * HH + nB] + bhh[0 * HH + nB];
    const float bBg = bih[2 * HH + nB] + bhh[2 * HH + nB];
    const float bBo = bih[3 * HH + nB] + bhh[3 * HH + nB];

    float wrA[4], wrB[4];
#pragma unroll
    for (int p = 0; p < 4; p++) {
        wrA[p] = Whr[p * HH + nA];
        wrB[p] = Whr[p * HH + nB];
    }

    float out[8][4];
#pragma unroll
    for (int t = 0; t < 8; t++) {
        const float cA = sig_fast(aAi[t] + bAi) * tanh_fast(aAg[t] + bAg);
        const float hA = sig_fast(aAo[t] + bAo) * tanh_fast(cA);
        const float cB = sig_fast(aBi[t] + bBi) * tanh_fast(aBg[t] + bBg);
        const float hB = sig_fast(aBo[t] + bBo) * tanh_fast(cB);
#pragma unroll
        for (int p = 0; p < 4; p++)
            out[t][p] = fmaf(hA, wrA[p], hB * wrB[p]);
    }

    // Butterfly reduce over the 32 hidden lanes of the warp
#pragma unroll
    for (int off = 16; off > 0; off >>= 1)
#pragma unroll
        for (int t = 0; t < 8; t++)
#pragma unroll
            for (int p = 0; p < 4; p++)
                out[t][p] += __shfl_xor_sync(0xffffffffu, out[t][p], off);

    // Lane (t*4+p) writes partial for (t, p) -- avoids dynamic reg indexing
    float v = 0.f;
#pragma unroll
    for (int t = 0; t < 8; t++)
#pragma unroll
        for (int p = 0; p < 4; p++)
            if (nt == t * 4 + p) v = out[t][p];

    const int tg = t0 + tt * 8 + (nt >> 2);
    g_part[(size_t)(tg * NCHUNK + nchunk) * 4 + (nt & 3)] = v;
}

// Sum the NCHUNK partials per timestep -> [T,4]
__global__ void reduce_part(float* __restrict__ dext, int dsel)
{
    float* dst = (dsel < 0) ? dext : g_ybuf[dsel];
    const int t = blockIdx.x * blockDim.x + threadIdx.x;
    if (t >= TT) return;
    const float4* p = (const float4*)g_part;
    float4 s = make_float4(0.f, 0.f, 0.f, 0.f);
#pragma unroll 8
    for (int c = 0; c < NCHUNK; c++) {
        const float4 v = p[(size_t)t * NCHUNK + c];
        s.x += v.x; s.y += v.y; s.z += v.z; s.w += v.w;
    }
    ((float4*)dst)[t] = s;
}

extern "C" void kernel_launch(void* const* d_in, const int* in_sizes, int n_in,
                              void* d_out, int out_size)
{
    (void)in_sizes; (void)n_in; (void)out_size;

    // metadata order: x, then per layer {W_ih, W_hh, b_ih, b_hh, W_hr}
    const float* x    = (const float*)d_in[0];
    const float* Wih0 = (const float*)d_in[1];
    const float* bih0 = (const float*)d_in[3];
    const float* bhh0 = (const float*)d_in[4];
    const float* Whr0 = (const float*)d_in[5];
    const float* Wih1 = (const float*)d_in[6];
    const float* bih1 = (const float*)d_in[8];
    const float* bhh1 = (const float*)d_in[9];
    const float* Whr1 = (const float*)d_in[10];
    const float* Wih2 = (const float*)d_in[11];
    const float* bih2 = (const float*)d_in[13];
    const float* bhh2 = (const float*)d_in[14];
    const float* Whr2 = (const float*)d_in[15];
    float* out = (float*)d_out;

    const dim3 gg(TT / TB, NCHUNK);

    // Layer 0 (K=64)
    gate_gemm<FF><<<gg, 256>>>(x, -1, Wih0, bih0, bhh0, Whr0);
    reduce_part<<<TT / 256, 256>>>(nullptr, 0);
    // Layer 1 (K=4)
    gate_gemm<PP><<<gg, 256>>>(nullptr, 0, Wih1, bih1, bhh1, Whr1);
    reduce_part<<<TT / 256, 256>>>(nullptr, 1);
    // Layer 2 (K=4)
    gate_gemm<PP><<<gg, 256>>>(nullptr, 1, Wih2, bih2, bhh2, Whr2);
    reduce_part<<<TT / 256, 256>>>(out, -1);
}

// round 7
// speedup vs baseline: 1.7699x; 1.7699x over previous
#include <cuda_runtime.h>

#define TT 8192
#define FF 64
#define HH 4096
#define PP 4

// Layer-0 tiling: 64 timesteps x 32 hidden rows per block
#define TB0 64
#define NC0 32
#define NCH0 (HH / NC0)     // 128 chunks

// Scratch (no allocation allowed -> __device__ globals)
__device__ __align__(16) float g_part[(size_t)TT * NCH0 * 4];  // 16 MB partials
__device__ __align__(16) float g_ybuf[2][TT * 4];              // inter-layer activations

__device__ __forceinline__ float tanh_fast(float x) {
    float y;
    asm("tanh.approx.f32 %0, %1;" : "=f"(y) : "f"(x));
    return y;
}
__device__ __forceinline__ float sig_fast(float x) {
    return 0.5f * tanh_fast(0.5f * x) + 0.5f;
}
__device__ __forceinline__ void dot4(float& acc, const float4 wv, const float4 xv) {
    acc = fmaf(wv.x, xv.x, acc);
    acc = fmaf(wv.y, xv.y, acc);
    acc = fmaf(wv.z, xv.z, acc);
    acc = fmaf(wv.w, xv.w, acc);
}

// ---------------------------------------------------------------------------
// Layer 0: gates GEMM (i,g,o; f is dead with zero state) + LSTM nonlinearity
// + W_hr projection -> per-chunk partials. Weights staged in smem (fixes the
// nL=32 L1tex wavefront bottleneck of the LDG version).
// Block: 256 thr = 8 warps; warp = 8 timesteps; lane = 1 hidden row.
// ---------------------------------------------------------------------------
__global__ __launch_bounds__(256)
void l0_gemm(const float* __restrict__ X,
             const float* __restrict__ Wih,
             const float* __restrict__ bih,
             const float* __restrict__ bhh,
             const float* __restrict__ Whr)
{
    __shared__ float xs[TB0 * FF];          // 16 KB
    __shared__ float ws[3][NC0][68];        // 26.1 KB (68-pad: conflict-free LDS.128)

    const int t0  = blockIdx.x * TB0;
    const int n0  = blockIdx.y * NC0;
    const int tid = threadIdx.x;

    // x tile: 1024 float4, coalesced
    {
        const float4* Xg  = (const float4*)(X + (size_t)t0 * FF);
        float4*       xs4 = (float4*)xs;
#pragma unroll
        for (int i = 0; i < 4; i++)
            xs4[tid + 256 * i] = Xg[tid + 256 * i];
    }
    // weight tiles: gates i(0), g(2), o(3); 512 float4 each, coalesced
    {
        const int gg[3] = {0, 2, 3};
#pragma unroll
        for (int g = 0; g < 3; g++) {
#pragma unroll
            for (int j = 0; j < 2; j++) {
                const int i = tid + 256 * j;       // 0..511
                const int r = i >> 4, c = i & 15;
                const float4 v =
                    ((const float4*)Wih)[(size_t)(gg[g] * HH + n0 + r) * 16 + c];
                *(float4*)&ws[g][r][c * 4] = v;
            }
        }
    }
    __syncthreads();

    const int nt = tid & 31;   // hidden row lane
    const int tt = tid >> 5;   // warp -> timestep subgroup
    const int n  = n0 + nt;

    float ai[8] = {}, ag[8] = {}, ao[8] = {};

#pragma unroll 4
    for (int k = 0; k < FF; k += 4) {
        const float4 wi = *(const float4*)&ws[0][nt][k];
        const float4 wg = *(const float4*)&ws[1][nt][k];
        const float4 wo = *(const float4*)&ws[2][nt][k];
#pragma unroll
        for (int t = 0; t < 8; t++) {
            const float4 x4 = *(const float4*)&xs[(tt * 8 + t) * FF + k];
            dot4(ai[t], wi, x4);
            dot4(ag[t], wg, x4);
            dot4(ao[t], wo, x4);
        }
    }

    const float bi = bih[n] + bhh[n];
    const float bg = bih[2 * HH + n] + bhh[2 * HH + n];
    const float bo = bih[3 * HH + n] + bhh[3 * HH + n];

    float wr[4];
#pragma unroll
    for (int p = 0; p < 4; p++) wr[p] = Whr[p * HH + n];

    float out[8][4];
#pragma unroll
    for (int t = 0; t < 8; t++) {
        const float c = sig_fast(ai[t] + bi) * tanh_fast(ag[t] + bg);
        const float h = sig_fast(ao[t] + bo) * tanh_fast(c);
#pragma unroll
        for (int p = 0; p < 4; p++) out[t][p] = h * wr[p];
    }

    // Butterfly reduce over the 32 hidden lanes
#pragma unroll
    for (int off = 16; off > 0; off >>= 1)
#pragma unroll
        for (int t = 0; t < 8; t++)
#pragma unroll
            for (int p = 0; p < 4; p++)
                out[t][p] += __shfl_xor_sync(0xffffffffu, out[t][p], off);

    // lane (t*4+p) holds result for (timestep t, proj p)
    float v = 0.f;
#pragma unroll
    for (int t = 0; t < 8; t++)
#pragma unroll
        for (int p = 0; p < 4; p++)
            if (nt == t * 4 + p) v = out[t][p];

    const int tg = t0 + tt * 8 + (nt >> 2);
    g_part[((size_t)tg * NCH0 + blockIdx.y) * 4 + (nt & 3)] = v;
}

// ---------------------------------------------------------------------------
// Layers 1/2 (K=4): one thread = one timestep, full dot in registers, weights
// streamed through smem (broadcast reads). Hidden split 4-ways across blocks.
// Block: 128 threads. Grid: (TT/128 / ... ) = (64, 4).
// ---------------------------------------------------------------------------
__global__ __launch_bounds__(128)
void l12_gemm(int xsel,
              const float* __restrict__ Wih,
              const float* __restrict__ bih,
              const float* __restrict__ bhh,
              const float* __restrict__ Whr)
{
    const float* __restrict__ Y = g_ybuf[xsel];

    __shared__ float4 wsg[3][128];   // gate weight rows (i,g,o)
    __shared__ float4 wrs[128];      // W_hr columns
    __shared__ float4 bss[128];      // fused biases (bi,bg,bo,-)

    const int tid = threadIdx.x;
    const int t   = blockIdx.x * 128 + tid;
    const int h0  = blockIdx.y * (HH / 4);

    const float4 y = ((const float4*)Y)[t];
    float a0 = 0.f, a1 = 0.f, a2 = 0.f, a3 = 0.f;

    const int gg[3] = {0, 2, 3};
    for (int tile = 0; tile < HH / 4; tile += 128) {
        __syncthreads();
        const int hr = h0 + tile + tid;
#pragma unroll
        for (int g = 0; g < 3; g++)
            wsg[g][tid] = ((const float4*)Wih)[gg[g] * HH + hr];
        {
            float4 wv;
            wv.x = Whr[0 * HH + hr];
            wv.y = Whr[1 * HH + hr];
            wv.z = Whr[2 * HH + hr];
            wv.w = Whr[3 * HH + hr];
            wrs[tid] = wv;
            float4 bv;
            bv.x = bih[hr] + bhh[hr];
            bv.y = bih[2 * HH + hr] + bhh[2 * HH + hr];
            bv.z = bih[3 * HH + hr] + bhh[3 * HH + hr];
            bv.w = 0.f;
            bss[tid] = bv;
        }
        __syncthreads();

#pragma unroll 4
        for (int r = 0; r < 128; r++) {
            const float4 wi = wsg[0][r];
            const float4 wg = wsg[1][r];
            const float4 wo = wsg[2][r];
            const float4 b  = bss[r];
            const float4 w  = wrs[r];
            float gi = b.x; dot4(gi, wi, y);
            float gv = b.y; dot4(gv, wg, y);
            float go = b.z; dot4(go, wo, y);
            const float c = sig_fast(gi) * tanh_fast(gv);
            const float h = sig_fast(go) * tanh_fast(c);
            a0 = fmaf(h, w.x, a0);
            a1 = fmaf(h, w.y, a1);
            a2 = fmaf(h, w.z, a2);
            a3 = fmaf(h, w.w, a3);
        }
    }

    ((float4*)g_part)[(size_t)t * 4 + blockIdx.y] = make_float4(a0, a1, a2, a3);
}

// Sum NCH partials per timestep -> [T,4]
template <int NCH>
__global__ void reduce_part_k(float* __restrict__ dext, int dsel)
{
    float* dst = (dsel < 0) ? dext : g_ybuf[dsel];
    const int t = blockIdx.x * blockDim.x + threadIdx.x;
    if (t >= TT) return;
    const float4* p = (const float4*)g_part + (size_t)t * NCH;
    float4 s = make_float4(0.f, 0.f, 0.f, 0.f);
#pragma unroll 8
    for (int c = 0; c < NCH; c++) {
        const float4 v = p[c];
        s.x += v.x; s.y += v.y; s.z += v.z; s.w += v.w;
    }
    ((float4*)dst)[t] = s;
}

extern "C" void kernel_launch(void* const* d_in, const int* in_sizes, int n_in,
                              void* d_out, int out_size)
{
    (void)in_sizes; (void)n_in; (void)out_size;

    const float* x    = (const float*)d_in[0];
    const float* Wih0 = (const float*)d_in[1];
    const float* bih0 = (const float*)d_in[3];
    const float* bhh0 = (const float*)d_in[4];
    const float* Whr0 = (const float*)d_in[5];
    const float* Wih1 = (const float*)d_in[6];
    const float* bih1 = (const float*)d_in[8];
    const float* bhh1 = (const float*)d_in[9];
    const float* Whr1 = (const float*)d_in[10];
    const float* Wih2 = (const float*)d_in[11];
    const float* bih2 = (const float*)d_in[13];
    const float* bhh2 = (const float*)d_in[14];
    const float* Whr2 = (const float*)d_in[15];
    float* out = (float*)d_out;

    // Layer 0
    l0_gemm<<<dim3(TT / TB0, NCH0), 256>>>(x, Wih0, bih0, bhh0, Whr0);
    reduce_part_k<NCH0><<<TT / 256, 256>>>(nullptr, 0);
    // Layer 1
    l12_gemm<<<dim3(TT / 128, 4), 128>>>(0, Wih1, bih1, bhh1, Whr1);
    reduce_part_k<4><<<TT / 256, 256>>>(nullptr, 1);
    // Layer 2
    l12_gemm<<<dim3(TT / 128, 4), 128>>>(1, Wih2, bih2, bhh2, Whr2);
    reduce_part_k<4><<<TT / 256, 256>>>(out, -1);
}

// round 10
// speedup vs baseline: 3.0253x; 1.7093x over previous
#include <cuda_runtime.h>
#include <cuda_bf16.h>
#include <cstdint>

#define TT 8192
#define FF 64
#define HH 4096
#define PP 4

// ===========================================================================
// Device scratch (no allocation allowed -> __device__ globals)
// ===========================================================================
__device__ __align__(16) float g_part[(size_t)TT * 512];       // 16 MB partials
__device__ __align__(16) float g_ybuf[2][TT * 4];              // inter-layer activations
// Split-bf16 copies (plain row-major)
__device__ __align__(16) __nv_bfloat16 g_xh[TT * FF];          // x hi
__device__ __align__(16) __nv_bfloat16 g_xl[TT * FF];          // x lo
__device__ __align__(16) __nv_bfloat16 g_wh[3 * HH * FF];      // W gates {i,g,o} hi
__device__ __align__(16) __nv_bfloat16 g_wl[3 * HH * FF];      // W gates {i,g,o} lo

__device__ __forceinline__ float tanh_fast(float x) {
    float y;
    asm("tanh.approx.f32 %0, %1;" : "=f"(y) : "f"(x));
    return y;
}
__device__ __forceinline__ float sig_fast(float x) {
    return 0.5f * tanh_fast(0.5f * x) + 0.5f;
}
__device__ __forceinline__ void dot4(float& acc, const float4 wv, const float4 xv) {
    acc = fmaf(wv.x, xv.x, acc);
    acc = fmaf(wv.y, xv.y, acc);
    acc = fmaf(wv.z, xv.z, acc);
    acc = fmaf(wv.w, xv.w, acc);
}

// bf16 HMMA m16n8k16 (baseline PTX feature -> compiles on compute_103)
__device__ __forceinline__ void mma16816(float d[4],
                                         uint32_t a0, uint32_t a1, uint32_t a2, uint32_t a3,
                                         uint32_t b0, uint32_t b1) {
    asm volatile(
        "mma.sync.aligned.m16n8k16.row.col.f32.bf16.bf16.f32 "
        "{%0,%1,%2,%3}, {%4,%5,%6,%7}, {%8,%9}, {%0,%1,%2,%3};"
        : "+f"(d[0]), "+f"(d[1]), "+f"(d[2]), "+f"(d[3])
        : "r"(a0), "r"(a1), "r"(a2), "r"(a3), "r"(b0), "r"(b1));
}

union BF8 { __nv_bfloat16 h[8]; uint4 v; };

__device__ __forceinline__ void cvt8(const float* src, uint4& hv, uint4& lv) {
    BF8 hb, lb;
#pragma unroll
    for (int j = 0; j < 8; j++) {
        const float v = src[j];
        const __nv_bfloat16 h = __float2bfloat16(v);
        hb.h[j] = h;
        lb.h[j] = __float2bfloat16(v - __bfloat162float(h));
    }
    hv = hb.v; lv = lb.v;
}

// ---------------------------------------------------------------------------
// Pre-convert W_ih_0 gate blocks {i,g,o} -> row-major bf16 hi/lo
// ---------------------------------------------------------------------------
__global__ __launch_bounds__(256)
void conv_w2(const float* __restrict__ Wih)
{
    const int idx = blockIdx.x * 256 + threadIdx.x;  // < 3*4096*8
    const int s = idx >> 15;
    const int r9 = idx & 32767;
    const int n = r9 >> 3;
    const int u = r9 & 7;
    const int gbrow = (s == 0) ? 0 : (s == 1) ? 2 * HH : 3 * HH;
    uint4 hv, lv;
    cvt8(Wih + (size_t)(gbrow + n) * FF + u * 8, hv, lv);
    const size_t o = (size_t)(s * HH + n) * 8 + u;
    ((uint4*)g_wh)[o] = hv;
    ((uint4*)g_wl)[o] = lv;
}

__global__ __launch_bounds__(256)
void conv_x2(const float* __restrict__ X)
{
    const int idx = blockIdx.x * 256 + threadIdx.x;  // < 8192*8
    const int t = idx >> 3, u = idx & 7;
    uint4 hv, lv;
    cvt8(X + (size_t)t * FF + u * 8, hv, lv);
    ((uint4*)g_xh)[(size_t)t * 8 + u] = hv;
    ((uint4*)g_xl)[(size_t)t * 8 + u] = lv;
}

// ---------------------------------------------------------------------------
// Layer 0 via mma.sync bf16 (split hi/lo, 3 passes):
//   gates[t,n] = x[t,:] . W[gate][n,:], then LSTM nonlinearity + W_hr proj.
// Block: 64 t x 32 n, 128 threads (4 warps = 4 t-subtiles of 16).
// Grid: (8192/64, 4096/32) = (128, 128).
// Smem tiles XOR-swizzled: 16B unit u of row r stored at u ^ (r&7).
// ---------------------------------------------------------------------------
__global__ __launch_bounds__(128)
void l0_mma(const float* __restrict__ bih,
            const float* __restrict__ bhh,
            const float* __restrict__ Whr)
{
    __shared__ __align__(16) __nv_bfloat16 xsh[64 * 64];       // 8 KB
    __shared__ __align__(16) __nv_bfloat16 xsl[64 * 64];       // 8 KB
    __shared__ __align__(16) __nv_bfloat16 wsh[3 * 32 * 64];   // 12 KB
    __shared__ __align__(16) __nv_bfloat16 wsl[3 * 32 * 64];   // 12 KB
    __shared__ float bias_s[3][32];
    __shared__ float whr_s[4][32];

    const int tid = threadIdx.x;
    const int wt  = tid >> 5;           // warp -> t-subtile (16 rows)
    const int lane = tid & 31;
    const int g5  = lane >> 2;          // mma groupID
    const int tid4 = lane & 3;
    const int t0  = blockIdx.x * 64;
    const int n0  = blockIdx.y * 32;

    // ---- stage x tile (64 rows x 8 units), swizzled ----
    {
        const uint4* sxh = (const uint4*)g_xh + (size_t)t0 * 8;
        const uint4* sxl = (const uint4*)g_xl + (size_t)t0 * 8;
        uint4* dxh = (uint4*)xsh;
        uint4* dxl = (uint4*)xsl;
#pragma unroll
        for (int it = 0; it < 4; it++) {
            const int i = tid + 128 * it;          // 0..511
            const int r = i >> 3, u = i & 7;
            const int d = r * 8 + (u ^ (r & 7));
            dxh[d] = sxh[i];
            dxl[d] = sxl[i];
        }
    }
    // ---- stage W tiles (3 gates x 32 rows x 8 units), swizzled ----
    {
        uint4* dwh = (uint4*)wsh;
        uint4* dwl = (uint4*)wsl;
#pragma unroll
        for (int it = 0; it < 6; it++) {
            const int i = tid + 128 * it;          // 0..767
            const int s = i >> 8;
            const int rem = i & 255;
            const int n = rem >> 3, u = rem & 7;
            const size_t src = (size_t)(s * HH + n0 + n) * 8 + u;
            const int d = (s * 32 + n) * 8 + (u ^ (n & 7));
            dwh[d] = ((const uint4*)g_wh)[src];
            dwl[d] = ((const uint4*)g_wl)[src];
        }
    }
    // ---- bias + whr ----
    if (tid < 32) {
        const int nn = n0 + tid;
        bias_s[0][tid] = bih[nn] + bhh[nn];
        bias_s[1][tid] = bih[2 * HH + nn] + bhh[2 * HH + nn];
        bias_s[2][tid] = bih[3 * HH + nn] + bhh[3 * HH + nn];
#pragma unroll
        for (int p = 0; p < 4; p++) whr_s[p][tid] = Whr[(size_t)p * HH + nn];
    }
    __syncthreads();

    // Accumulators: [n-subtile j][gate][frag]
    float d[4][3][4];
#pragma unroll
    for (int j = 0; j < 4; j++)
#pragma unroll
        for (int g = 0; g < 3; g++)
#pragma unroll
            for (int e = 0; e < 4; e++) d[j][g][e] = 0.f;

    // A rows for this warp: ra = wt*16 + g5 (+8)
    const int ra0 = wt * 16 + g5;
    const int ra1 = ra0 + 8;
    const int xr0 = (ra0 & 7) << 4;   // XOR byte pattern
    const int xr1 = (ra1 & 7) << 4;
    const char* cxh = (const char*)xsh;
    const char* cxl = (const char*)xsl;
    const char* cwh = (const char*)wsh;
    const char* cwl = (const char*)wsl;

#pragma unroll
    for (int ks = 0; ks < 4; ks++) {
        const int kb0 = ks * 32 + tid4 * 4;   // bytes, cols tid4*2
        const int kb1 = kb0 + 16;             // cols +8
        const uint32_t ah0 = *(const uint32_t*)(cxh + ra0 * 128 + (kb0 ^ xr0));
        const uint32_t ah1 = *(const uint32_t*)(cxh + ra1 * 128 + (kb0 ^ xr1));
        const uint32_t ah2 = *(const uint32_t*)(cxh + ra0 * 128 + (kb1 ^ xr0));
        const uint32_t ah3 = *(const uint32_t*)(cxh + ra1 * 128 + (kb1 ^ xr1));
        const uint32_t al0 = *(const uint32_t*)(cxl + ra0 * 128 + (kb0 ^ xr0));
        const uint32_t al1 = *(const uint32_t*)(cxl + ra1 * 128 + (kb0 ^ xr1));
        const uint32_t al2 = *(const uint32_t*)(cxl + ra0 * 128 + (kb1 ^ xr0));
        const uint32_t al3 = *(const uint32_t*)(cxl + ra1 * 128 + (kb1 ^ xr1));

#pragma unroll
        for (int g = 0; g < 3; g++) {
#pragma unroll
            for (int j = 0; j < 4; j++) {
                const int nrow = j * 8 + g5;          // row within 32-row gate tile
                const int roff = (g * 32 + nrow) * 128;
                const int xrn = (nrow & 7) << 4;
                const uint32_t bh0 = *(const uint32_t*)(cwh + roff + (kb0 ^ xrn));
                const uint32_t bh1 = *(const uint32_t*)(cwh + roff + (kb1 ^ xrn));
                const uint32_t bl0 = *(const uint32_t*)(cwl + roff + (kb0 ^ xrn));
                const uint32_t bl1 = *(const uint32_t*)(cwl + roff + (kb1 ^ xrn));
                mma16816(d[j][g], ah0, ah1, ah2, ah3, bh0, bh1);
                mma16816(d[j][g], ah0, ah1, ah2, ah3, bl0, bl1);
                mma16816(d[j][g], al0, al1, al2, al3, bh0, bh1);
            }
        }
    }

    // ---- epilogue: bias + LSTM cell + W_hr projection ----
    float hs[2][4];
#pragma unroll
    for (int r = 0; r < 2; r++)
#pragma unroll
        for (int p = 0; p < 4; p++) hs[r][p] = 0.f;

#pragma unroll
    for (int j = 0; j < 4; j++) {
#pragma unroll
        for (int e = 0; e < 4; e++) {
            const int rh = e >> 1, c = e & 1;
            const int nl = j * 8 + tid4 * 2 + c;
            const float gi = d[j][0][e] + bias_s[0][nl];
            const float gg = d[j][1][e] + bias_s[1][nl];
            const float go = d[j][2][e] + bias_s[2][nl];
            const float cc = sig_fast(gi) * tanh_fast(gg);
            const float h  = sig_fast(go) * tanh_fast(cc);
#pragma unroll
            for (int p = 0; p < 4; p++)
                hs[rh][p] = fmaf(h, whr_s[p][nl], hs[rh][p]);
        }
    }

    // reduce over the 4 tid4 lanes (quad)
#pragma unroll
    for (int off = 1; off <= 2; off <<= 1)
#pragma unroll
        for (int r = 0; r < 2; r++)
#pragma unroll
            for (int p = 0; p < 4; p++)
                hs[r][p] += __shfl_xor_sync(0xffffffffu, hs[r][p], off);

    if (tid4 == 0) {
        const int tg0 = t0 + wt * 16 + g5;
        ((float4*)g_part)[(size_t)tg0 * 128 + blockIdx.y] =
            make_float4(hs[0][0], hs[0][1], hs[0][2], hs[0][3]);
        ((float4*)g_part)[(size_t)(tg0 + 8) * 128 + blockIdx.y] =
            make_float4(hs[1][0], hs[1][1], hs[1][2], hs[1][3]);
    }
}

// ---------------------------------------------------------------------------
// Layers 1/2 (K=4): one thread = one timestep (proven kernel, unchanged)
// ---------------------------------------------------------------------------
__global__ __launch_bounds__(128)
void l12_gemm(int xsel,
              const float* __restrict__ Wih,
              const float* __restrict__ bih,
              const float* __restrict__ bhh,
              const float* __restrict__ Whr)
{
    const float* __restrict__ Y = g_ybuf[xsel];

    __shared__ float4 wsg[3][128];
    __shared__ float4 wrs[128];
    __shared__ float4 bss[128];

    const int tid = threadIdx.x;
    const int t   = blockIdx.x * 128 + tid;
    const int h0  = blockIdx.y * (HH / 4);

    const float4 y = ((const float4*)Y)[t];
    float a0 = 0.f, a1 = 0.f, a2 = 0.f, a3 = 0.f;

    const int gg[3] = {0, 2, 3};
    for (int tile = 0; tile < HH / 4; tile += 128) {
        __syncthreads();
        const int hr = h0 + tile + tid;
#pragma unroll
        for (int g = 0; g < 3; g++)
            wsg[g][tid] = ((const float4*)Wih)[gg[g] * HH + hr];
        {
            float4 wv;
            wv.x = Whr[0 * HH + hr];
            wv.y = Whr[1 * HH + hr];
            wv.z = Whr[2 * HH + hr];
            wv.w = Whr[3 * HH + hr];
            wrs[tid] = wv;
            float4 bv;
            bv.x = bih[hr] + bhh[hr];
            bv.y = bih[2 * HH + hr] + bhh[2 * HH + hr];
            bv.z = bih[3 * HH + hr] + bhh[3 * HH + hr];
            bv.w = 0.f;
            bss[tid] = bv;
        }
        __syncthreads();

#pragma unroll 4
        for (int r = 0; r < 128; r++) {
            const float4 wi = wsg[0][r];
            const float4 wg = wsg[1][r];
            const float4 wo = wsg[2][r];
            const float4 b  = bss[r];
            const float4 w  = wrs[r];
            float gi = b.x; dot4(gi, wi, y);
            float gv = b.y; dot4(gv, wg, y);
            float go = b.z; dot4(go, wo, y);
            const float c = sig_fast(gi) * tanh_fast(gv);
            const float h = sig_fast(go) * tanh_fast(c);
            a0 = fmaf(h, w.x, a0);
            a1 = fmaf(h, w.y, a1);
            a2 = fmaf(h, w.z, a2);
            a3 = fmaf(h, w.w, a3);
        }
    }

    ((float4*)g_part)[(size_t)t * 4 + blockIdx.y] = make_float4(a0, a1, a2, a3);
}

// Sum NCH partials per timestep -> [T,4]
template <int NCH>
__global__ void reduce_part_k(float* __restrict__ dext, int dsel)
{
    float* dst = (dsel < 0) ? dext : g_ybuf[dsel];
    const int t = blockIdx.x * blockDim.x + threadIdx.x;
    if (t >= TT) return;
    const float4* p = (const float4*)g_part + (size_t)t * NCH;
    float4 s = make_float4(0.f, 0.f, 0.f, 0.f);
#pragma unroll 8
    for (int c = 0; c < NCH; c++) {
        const float4 v = p[c];
        s.x += v.x; s.y += v.y; s.z += v.z; s.w += v.w;
    }
    ((float4*)dst)[t] = s;
}

extern "C" void kernel_launch(void* const* d_in, const int* in_sizes, int n_in,
                              void* d_out, int out_size)
{
    (void)in_sizes; (void)n_in; (void)out_size;

    const float* x    = (const float*)d_in[0];
    const float* Wih0 = (const float*)d_in[1];
    const float* bih0 = (const float*)d_in[3];
    const float* bhh0 = (const float*)d_in[4];
    const float* Whr0 = (const float*)d_in[5];
    const float* Wih1 = (const float*)d_in[6];
    const float* bih1 = (const float*)d_in[8];
    const float* bhh1 = (const float*)d_in[9];
    const float* Whr1 = (const float*)d_in[10];
    const float* Wih2 = (const float*)d_in[11];
    const float* bih2 = (const float*)d_in[13];
    const float* bhh2 = (const float*)d_in[14];
    const float* Whr2 = (const float*)d_in[15];
    float* out = (float*)d_out;

    // Pre-convert to split-bf16
    conv_w2<<<384, 256>>>(Wih0);
    conv_x2<<<256, 256>>>(x);

    // Layer 0: tensor cores (mma.sync) + fused epilogue
    l0_mma<<<dim3(128, 128), 128>>>(bih0, bhh0, Whr0);
    reduce_part_k<128><<<TT / 256, 256>>>(nullptr, 0);

    // Layer 1
    l12_gemm<<<dim3(TT / 128, 4), 128>>>(0, Wih1, bih1, bhh1, Whr1);
    reduce_part_k<4><<<TT / 256, 256>>>(nullptr, 1);
    // Layer 2
    l12_gemm<<<dim3(TT / 128, 4), 128>>>(1, Wih2, bih2, bhh2, Whr2);
    reduce_part_k<4><<<TT / 256, 256>>>(out, -1);
}

// round 11
// speedup vs baseline: 3.9061x; 1.2911x over previous
#include <cuda_runtime.h>
#include <cuda_bf16.h>
#include <cstdint>

#define TT 8192
#define FF 64
#define HH 4096
#define PP 4

// ===========================================================================
// Device scratch (no allocation allowed -> __device__ globals)
// Partials stored TRANSPOSED: [chunk][t] (coalesced reduce reads)
// ===========================================================================
__device__ __align__(16) float g_part[(size_t)8192 * 1024];    // 33.5 MB (256 chunks x T x 4)
__device__ __align__(16) float g_p2[8 * TT * 4];               // stage-1 output (8 chunks)
__device__ __align__(16) float g_ybuf[2][TT * 4];              // inter-layer activations
// Split-bf16 copies (plain row-major)
__device__ __align__(16) __nv_bfloat16 g_xh[TT * FF];
__device__ __align__(16) __nv_bfloat16 g_xl[TT * FF];
__device__ __align__(16) __nv_bfloat16 g_wh[3 * HH * FF];
__device__ __align__(16) __nv_bfloat16 g_wl[3 * HH * FF];

__device__ __forceinline__ float tanh_fast(float x) {
    float y;
    asm("tanh.approx.f32 %0, %1;" : "=f"(y) : "f"(x));
    return y;
}
__device__ __forceinline__ float sig_fast(float x) {
    return 0.5f * tanh_fast(0.5f * x) + 0.5f;
}
__device__ __forceinline__ void dot4(float& acc, const float4 wv, const float4 xv) {
    acc = fmaf(wv.x, xv.x, acc);
    acc = fmaf(wv.y, xv.y, acc);
    acc = fmaf(wv.z, xv.z, acc);
    acc = fmaf(wv.w, xv.w, acc);
}

// bf16 HMMA m16n8k16 (baseline PTX feature -> compiles on compute_103)
__device__ __forceinline__ void mma16816(float d[4],
                                         uint32_t a0, uint32_t a1, uint32_t a2, uint32_t a3,
                                         uint32_t b0, uint32_t b1) {
    asm volatile(
        "mma.sync.aligned.m16n8k16.row.col.f32.bf16.bf16.f32 "
        "{%0,%1,%2,%3}, {%4,%5,%6,%7}, {%8,%9}, {%0,%1,%2,%3};"
        : "+f"(d[0]), "+f"(d[1]), "+f"(d[2]), "+f"(d[3])
        : "r"(a0), "r"(a1), "r"(a2), "r"(a3), "r"(b0), "r"(b1));
}

union BF8 { __nv_bfloat16 h[8]; uint4 v; };

__device__ __forceinline__ void cvt8(const float* src, uint4& hv, uint4& lv) {
    BF8 hb, lb;
#pragma unroll
    for (int j = 0; j < 8; j++) {
        const float v = src[j];
        const __nv_bfloat16 h = __float2bfloat16(v);
        hb.h[j] = h;
        lb.h[j] = __float2bfloat16(v - __bfloat162float(h));
    }
    hv = hb.v; lv = lb.v;
}

__global__ __launch_bounds__(256)
void conv_w2(const float* __restrict__ Wih)
{
    const int idx = blockIdx.x * 256 + threadIdx.x;  // < 3*4096*8
    const int s = idx >> 15;
    const int r9 = idx & 32767;
    const int n = r9 >> 3;
    const int u = r9 & 7;
    const int gbrow = (s == 0) ? 0 : (s == 1) ? 2 * HH : 3 * HH;
    uint4 hv, lv;
    cvt8(Wih + (size_t)(gbrow + n) * FF + u * 8, hv, lv);
    const size_t o = (size_t)(s * HH + n) * 8 + u;
    ((uint4*)g_wh)[o] = hv;
    ((uint4*)g_wl)[o] = lv;
}

__global__ __launch_bounds__(256)
void conv_x2(const float* __restrict__ X)
{
    const int idx = blockIdx.x * 256 + threadIdx.x;  // < 8192*8
    const int t = idx >> 3, u = idx & 7;
    uint4 hv, lv;
    cvt8(X + (size_t)t * FF + u * 8, hv, lv);
    ((uint4*)g_xh)[(size_t)t * 8 + u] = hv;
    ((uint4*)g_xl)[(size_t)t * 8 + u] = lv;
}

// ---------------------------------------------------------------------------
// Layer 0 via mma.sync bf16 (split hi/lo, 3 passes).
// Block: 64 t x 32 n, 128 threads. Warp tile: 32 t x 16 n (wt -> tg=wt>>1,
// ng=wt&1) for 2x B-fragment reuse vs R10. Grid: (128, 128).
// Smem tiles XOR-swizzled: 16B unit u of row r stored at u ^ (r&7).
// Partials written transposed: chunk = blockIdx.y*2+ng (256 chunks of 16 n).
// ---------------------------------------------------------------------------
__global__ __launch_bounds__(128)
void l0_mma(const float* __restrict__ bih,
            const float* __restrict__ bhh,
            const float* __restrict__ Whr)
{
    __shared__ __align__(16) __nv_bfloat16 xsh[64 * 64];       // 8 KB
    __shared__ __align__(16) __nv_bfloat16 xsl[64 * 64];       // 8 KB
    __shared__ __align__(16) __nv_bfloat16 wsh[3 * 32 * 64];   // 12 KB
    __shared__ __align__(16) __nv_bfloat16 wsl[3 * 32 * 64];   // 12 KB
    __shared__ float bias_s[3][32];
    __shared__ float whr_s[4][32];

    const int tid  = threadIdx.x;
    const int wt   = tid >> 5;
    const int tg   = wt >> 1;           // t half (32 rows)
    const int ng   = wt & 1;            // n half (16 cols)
    const int lane = tid & 31;
    const int g5   = lane >> 2;
    const int tid4 = lane & 3;
    const int t0   = blockIdx.x * 64;
    const int n0   = blockIdx.y * 32;

    // ---- stage x tile (64 rows x 8 units), swizzled ----
    {
        const uint4* sxh = (const uint4*)g_xh + (size_t)t0 * 8;
        const uint4* sxl = (const uint4*)g_xl + (size_t)t0 * 8;
        uint4* dxh = (uint4*)xsh;
        uint4* dxl = (uint4*)xsl;
#pragma unroll
        for (int it = 0; it < 4; it++) {
            const int i = tid + 128 * it;
            const int r = i >> 3, u = i & 7;
            const int d = r * 8 + (u ^ (r & 7));
            dxh[d] = sxh[i];
            dxl[d] = sxl[i];
        }
    }
    // ---- stage W tiles (3 gates x 32 rows x 8 units), swizzled ----
    {
        uint4* dwh = (uint4*)wsh;
        uint4* dwl = (uint4*)wsl;
#pragma unroll
        for (int it = 0; it < 6; it++) {
            const int i = tid + 128 * it;
            const int s = i >> 8;
            const int rem = i & 255;
            const int n = rem >> 3, u = rem & 7;
            const size_t src = (size_t)(s * HH + n0 + n) * 8 + u;
            const int d = (s * 32 + n) * 8 + (u ^ (n & 7));
            dwh[d] = ((const uint4*)g_wh)[src];
            dwl[d] = ((const uint4*)g_wl)[src];
        }
    }
    if (tid < 32) {
        const int nn = n0 + tid;
        bias_s[0][tid] = bih[nn] + bhh[nn];
        bias_s[1][tid] = bih[2 * HH + tid + n0] + bhh[2 * HH + nn];
        bias_s[2][tid] = bih[3 * HH + nn] + bhh[3 * HH + nn];
#pragma unroll
        for (int p = 0; p < 4; p++) whr_s[p][tid] = Whr[(size_t)p * HH + nn];
    }
    __syncthreads();

    // Accumulators: [t-set s][n-subtile j][gate][frag]
    float d[2][2][3][4];
#pragma unroll
    for (int s = 0; s < 2; s++)
#pragma unroll
        for (int j = 0; j < 2; j++)
#pragma unroll
            for (int g = 0; g < 3; g++)
#pragma unroll
                for (int e = 0; e < 4; e++) d[s][j][g][e] = 0.f;

    const char* cxh = (const char*)xsh;
    const char* cxl = (const char*)xsl;
    const char* cwh = (const char*)wsh;
    const char* cwl = (const char*)wsl;

#pragma unroll
    for (int ks = 0; ks < 4; ks++) {
        const int kb0 = ks * 32 + tid4 * 4;
        const int kb1 = kb0 + 16;

        uint32_t ah[2][4], al[2][4];
#pragma unroll
        for (int s = 0; s < 2; s++) {
            const int r0 = tg * 32 + s * 16 + g5;
            const int r1 = r0 + 8;
            const int x0 = (r0 & 7) << 4;
            const int x1 = (r1 & 7) << 4;
            ah[s][0] = *(const uint32_t*)(cxh + r0 * 128 + (kb0 ^ x0));
            ah[s][1] = *(const uint32_t*)(cxh + r1 * 128 + (kb0 ^ x1));
            ah[s][2] = *(const uint32_t*)(cxh + r0 * 128 + (kb1 ^ x0));
            ah[s][3] = *(const uint32_t*)(cxh + r1 * 128 + (kb1 ^ x1));
            al[s][0] = *(const uint32_t*)(cxl + r0 * 128 + (kb0 ^ x0));
            al[s][1] = *(const uint32_t*)(cxl + r1 * 128 + (kb0 ^ x1));
            al[s][2] = *(const uint32_t*)(cxl + r0 * 128 + (kb1 ^ x0));
            al[s][3] = *(const uint32_t*)(cxl + r1 * 128 + (kb1 ^ x1));
        }

#pragma unroll
        for (int g = 0; g < 3; g++) {
#pragma unroll
            for (int j = 0; j < 2; j++) {
                const int nrow = ng * 16 + j * 8 + g5;
                const int roff = (g * 32 + nrow) * 128;
                const int xrn = (nrow & 7) << 4;
                const uint32_t bh0 = *(const uint32_t*)(cwh + roff + (kb0 ^ xrn));
                const uint32_t bh1 = *(const uint32_t*)(cwh + roff + (kb1 ^ xrn));
                const uint32_t bl0 = *(const uint32_t*)(cwl + roff + (kb0 ^ xrn));
                const uint32_t bl1 = *(const uint32_t*)(cwl + roff + (kb1 ^ xrn));
#pragma unroll
                for (int s = 0; s < 2; s++) {
                    mma16816(d[s][j][g], ah[s][0], ah[s][1], ah[s][2], ah[s][3], bh0, bh1);
                    mma16816(d[s][j][g], ah[s][0], ah[s][1], ah[s][2], ah[s][3], bl0, bl1);
                    mma16816(d[s][j][g], al[s][0], al[s][1], al[s][2], al[s][3], bh0, bh1);
                }
            }
        }
    }

    // ---- epilogue: bias + LSTM cell + W_hr projection ----
    float hs[2][2][4];      // [s][row-half][p]
#pragma unroll
    for (int s = 0; s < 2; s++)
#pragma unroll
        for (int r = 0; r < 2; r++)
#pragma unroll
            for (int p = 0; p < 4; p++) hs[s][r][p] = 0.f;

#pragma unroll
    for (int s = 0; s < 2; s++) {
#pragma unroll
        for (int j = 0; j < 2; j++) {
#pragma unroll
            for (int e = 0; e < 4; e++) {
                const int rh = e >> 1, c = e & 1;
                const int nl = ng * 16 + j * 8 + tid4 * 2 + c;
                const float gi = d[s][j][0][e] + bias_s[0][nl];
                const float gg = d[s][j][1][e] + bias_s[1][nl];
                const float go = d[s][j][2][e] + bias_s[2][nl];
                const float cc = sig_fast(gi) * tanh_fast(gg);
                const float h  = sig_fast(go) * tanh_fast(cc);
#pragma unroll
                for (int p = 0; p < 4; p++)
                    hs[s][rh][p] = fmaf(h, whr_s[p][nl], hs[s][rh][p]);
            }
        }
    }

    // reduce over the 4 tid4 lanes (quad) -> sums this warp's 16 n-cols
#pragma unroll
    for (int off = 1; off <= 2; off <<= 1)
#pragma unroll
        for (int s = 0; s < 2; s++)
#pragma unroll
            for (int r = 0; r < 2; r++)
#pragma unroll
                for (int p = 0; p < 4; p++)
                    hs[s][r][p] += __shfl_xor_sync(0xffffffffu, hs[s][r][p], off);

    if (tid4 == 0) {
        const int chunk = blockIdx.y * 2 + ng;
#pragma unroll
        for (int s = 0; s < 2; s++)
#pragma unroll
            for (int r = 0; r < 2; r++) {
                const int tgl = t0 + tg * 32 + s * 16 + g5 + r * 8;
                ((float4*)g_part)[(size_t)chunk * TT + tgl] =
                    make_float4(hs[s][r][0], hs[s][r][1], hs[s][r][2], hs[s][r][3]);
            }
    }
}

// Stage 1: fold 256 chunks -> 8. Grid (TT/256, 8), 256 thr. Coalesced.
__global__ __launch_bounds__(256)
void reduce_stage1()
{
    const int t  = blockIdx.x * 256 + threadIdx.x;
    const int cg = blockIdx.y;
    const float4* p = (const float4*)g_part;
    float4 s = make_float4(0.f, 0.f, 0.f, 0.f);
#pragma unroll 8
    for (int c = cg * 32; c < cg * 32 + 32; c++) {
        const float4 v = p[(size_t)c * TT + t];
        s.x += v.x; s.y += v.y; s.z += v.z; s.w += v.w;
    }
    ((float4*)g_p2)[(size_t)cg * TT + t] = s;
}

// ---------------------------------------------------------------------------
// Layers 1/2 (K=4): one thread = one timestep. Hidden split 8-way (occupancy).
// Grid (TT/128, 8). Writes transposed partials [chunk][t].
// ---------------------------------------------------------------------------
__global__ __launch_bounds__(128)
void l12_gemm(int xsel,
              const float* __restrict__ Wih,
              const float* __restrict__ bih,
              const float* __restrict__ bhh,
              const float* __restrict__ Whr)
{
    const float* __restrict__ Y = g_ybuf[xsel];

    __shared__ float4 wsg[3][128];
    __shared__ float4 wrs[128];
    __shared__ float4 bss[128];

    const int tid = threadIdx.x;
    const int t   = blockIdx.x * 128 + tid;
    const int h0  = blockIdx.y * (HH / 8);

    const float4 y = ((const float4*)Y)[t];
    float a0 = 0.f, a1 = 0.f, a2 = 0.f, a3 = 0.f;

    const int gg[3] = {0, 2, 3};
    for (int tile = 0; tile < HH / 8; tile += 128) {
        __syncthreads();
        const int hr = h0 + tile + tid;
#pragma unroll
        for (int g = 0; g < 3; g++)
            wsg[g][tid] = ((const float4*)Wih)[gg[g] * HH + hr];
        {
            float4 wv;
            wv.x = Whr[0 * HH + hr];
            wv.y = Whr[1 * HH + hr];
            wv.z = Whr[2 * HH + hr];
            wv.w = Whr[3 * HH + hr];
            wrs[tid] = wv;
            float4 bv;
            bv.x = bih[hr] + bhh[hr];
            bv.y = bih[2 * HH + hr] + bhh[2 * HH + hr];
            bv.z = bih[3 * HH + hr] + bhh[3 * HH + hr];
            bv.w = 0.f;
            bss[tid] = bv;
        }
        __syncthreads();

#pragma unroll 4
        for (int r = 0; r < 128; r++) {
            const float4 wi = wsg[0][r];
            const float4 wg = wsg[1][r];
            const float4 wo = wsg[2][r];
            const float4 b  = bss[r];
            const float4 w  = wrs[r];
            float gi = b.x; dot4(gi, wi, y);
            float gv = b.y; dot4(gv, wg, y);
            float go = b.z; dot4(go, wo, y);
            const float c = sig_fast(gi) * tanh_fast(gv);
            const float h = sig_fast(go) * tanh_fast(c);
            a0 = fmaf(h, w.x, a0);
            a1 = fmaf(h, w.y, a1);
            a2 = fmaf(h, w.z, a2);
            a3 = fmaf(h, w.w, a3);
        }
    }

    ((float4*)g_part)[(size_t)blockIdx.y * TT + t] = make_float4(a0, a1, a2, a3);
}

// Final fold of NCH transposed chunks -> [T,4].  src: 0 = g_part, 1 = g_p2
template <int NCH>
__global__ void reduce_part_k(float* __restrict__ dext, int dsel, int ssel)
{
    float* dst = (dsel < 0) ? dext : g_ybuf[dsel];
    const float* src = ssel ? g_p2 : g_part;
    const int t = blockIdx.x * blockDim.x + threadIdx.x;
    if (t >= TT) return;
    const float4* p = (const float4*)src;
    float4 s = make_float4(0.f, 0.f, 0.f, 0.f);
#pragma unroll
    for (int c = 0; c < NCH; c++) {
        const float4 v = p[(size_t)c * TT + t];
        s.x += v.x; s.y += v.y; s.z += v.z; s.w += v.w;
    }
    ((float4*)dst)[t] = s;
}

extern "C" void kernel_launch(void* const* d_in, const int* in_sizes, int n_in,
                              void* d_out, int out_size)
{
    (void)in_sizes; (void)n_in; (void)out_size;

    const float* x    = (const float*)d_in[0];
    const float* Wih0 = (const float*)d_in[1];
    const float* bih0 = (const float*)d_in[3];
    const float* bhh0 = (const float*)d_in[4];
    const float* Whr0 = (const float*)d_in[5];
    const float* Wih1 = (const float*)d_in[6];
    const float* bih1 = (const float*)d_in[8];
    const float* bhh1 = (const float*)d_in[9];
    const float* Whr1 = (const float*)d_in[10];
    const float* Wih2 = (const float*)d_in[11];
    const float* bih2 = (const float*)d_in[13];
    const float* bhh2 = (const float*)d_in[14];
    const float* Whr2 = (const float*)d_in[15];
    float* out = (float*)d_out;

    // Pre-convert to split-bf16
    conv_w2<<<384, 256>>>(Wih0);
    conv_x2<<<256, 256>>>(x);

    // Layer 0: tensor cores (mma.sync) + fused epilogue, two-stage reduce
    l0_mma<<<dim3(128, 128), 128>>>(bih0, bhh0, Whr0);
    reduce_stage1<<<dim3(TT / 256, 8), 256>>>();
    reduce_part_k<8><<<TT / 256, 256>>>(nullptr, 0, 1);

    // Layer 1
    l12_gemm<<<dim3(TT / 128, 8), 128>>>(0, Wih1, bih1, bhh1, Whr1);
    reduce_part_k<8><<<TT / 256, 256>>>(nullptr, 1, 0);
    // Layer 2
    l12_gemm<<<dim3(TT / 128, 8), 128>>>(1, Wih2, bih2, bhh2, Whr2);
    reduce_part_k<8><<<TT / 256, 256>>>(out, -1, 0);
}

// round 12
// speedup vs baseline: 4.0160x; 1.0281x over previous
#include <cuda_runtime.h>
#include <cuda_bf16.h>
#include <cstdint>

#define TT 8192
#define FF 64
#define HH 4096
#define PP 4

// ===========================================================================
// Device scratch (no allocation allowed -> __device__ globals)
// Partials stored TRANSPOSED: [chunk][t] (coalesced reduce reads)
// ===========================================================================
__device__ __align__(16) float g_part[(size_t)64 * TT * 4];    // 8.4 MB (64 chunks)
__device__ __align__(16) float g_p2[8 * TT * 4];               // stage-1 output (8 chunks)
__device__ __align__(16) float g_ybuf[2][TT * 4];              // inter-layer activations
// Split-bf16 copies (plain row-major)
__device__ __align__(16) __nv_bfloat16 g_xh[TT * FF];
__device__ __align__(16) __nv_bfloat16 g_xl[TT * FF];
__device__ __align__(16) __nv_bfloat16 g_wh[3 * HH * FF];
__device__ __align__(16) __nv_bfloat16 g_wl[3 * HH * FF];

__device__ __forceinline__ float tanh_fast(float x) {
    float y;
    asm("tanh.approx.f32 %0, %1;" : "=f"(y) : "f"(x));
    return y;
}
__device__ __forceinline__ float sig_fast(float x) {
    return 0.5f * tanh_fast(0.5f * x) + 0.5f;
}
__device__ __forceinline__ void dot4(float& acc, const float4 wv, const float4 xv) {
    acc = fmaf(wv.x, xv.x, acc);
    acc = fmaf(wv.y, xv.y, acc);
    acc = fmaf(wv.z, xv.z, acc);
    acc = fmaf(wv.w, xv.w, acc);
}

// bf16 HMMA m16n8k16 (baseline PTX feature -> compiles on compute_103)
__device__ __forceinline__ void mma16816(float d[4],
                                         uint32_t a0, uint32_t a1, uint32_t a2, uint32_t a3,
                                         uint32_t b0, uint32_t b1) {
    asm volatile(
        "mma.sync.aligned.m16n8k16.row.col.f32.bf16.bf16.f32 "
        "{%0,%1,%2,%3}, {%4,%5,%6,%7}, {%8,%9}, {%0,%1,%2,%3};"
        : "+f"(d[0]), "+f"(d[1]), "+f"(d[2]), "+f"(d[3])
        : "r"(a0), "r"(a1), "r"(a2), "r"(a3), "r"(b0), "r"(b1));
}

union BF8 { __nv_bfloat16 h[8]; uint4 v; };

__device__ __forceinline__ void cvt8(const float* src, uint4& hv, uint4& lv) {
    BF8 hb, lb;
#pragma unroll
    for (int j = 0; j < 8; j++) {
        const float v = src[j];
        const __nv_bfloat16 h = __float2bfloat16(v);
        hb.h[j] = h;
        lb.h[j] = __float2bfloat16(v - __bfloat162float(h));
    }
    hv = hb.v; lv = lb.v;
}

__global__ __launch_bounds__(256)
void conv_w2(const float* __restrict__ Wih)
{
    const int idx = blockIdx.x * 256 + threadIdx.x;  // < 3*4096*8
    const int s = idx >> 15;
    const int r9 = idx & 32767;
    const int n = r9 >> 3;
    const int u = r9 & 7;
    const int gbrow = (s == 0) ? 0 : (s == 1) ? 2 * HH : 3 * HH;
    uint4 hv, lv;
    cvt8(Wih + (size_t)(gbrow + n) * FF + u * 8, hv, lv);
    const size_t o = (size_t)(s * HH + n) * 8 + u;
    ((uint4*)g_wh)[o] = hv;
    ((uint4*)g_wl)[o] = lv;
}

__global__ __launch_bounds__(256)
void conv_x2(const float* __restrict__ X)
{
    const int idx = blockIdx.x * 256 + threadIdx.x;  // < 8192*8
    const int t = idx >> 3, u = idx & 7;
    uint4 hv, lv;
    cvt8(X + (size_t)t * FF + u * 8, hv, lv);
    ((uint4*)g_xh)[(size_t)t * 8 + u] = hv;
    ((uint4*)g_xl)[(size_t)t * 8 + u] = lv;
}

// ---------------------------------------------------------------------------
// Layer 0 via mma.sync bf16 (split hi/lo, 3 passes).
// Block: 128 t x 64 n, 256 threads = 8 warps of 32t x 32n (tg = wt>>1 t-quarter,
// ng = wt&1 n-half). Grid: (64, 64). Smem XOR-swizzle: unit u of row r at
// u ^ (r&7). Per-block n-fold in smem -> 64 chunks of 64 n.
// Dynamic smem layout (bytes):
//   xsh 0 (16K) | xsl 16384 (16K) | wsh 32768 (24K) | wsl 57344 (24K)
//   bias 81920 (768) | whr 82688 (1K) | red 83712 (2K)  -> 85760 total
// ---------------------------------------------------------------------------
#define OFF_XSL  16384
#define OFF_WSH  32768
#define OFF_WSL  57344
#define OFF_BIAS 81920
#define OFF_WHR  82688
#define OFF_RED  83712
#define L0_SMEM  86016

__global__ __launch_bounds__(256, 2)
void l0_mma(const float* __restrict__ bih,
            const float* __restrict__ bhh,
            const float* __restrict__ Whr)
{
    extern __shared__ __align__(128) char smem[];
    char* cxh = smem;
    char* cxl = smem + OFF_XSL;
    char* cwh = smem + OFF_WSH;
    char* cwl = smem + OFF_WSL;
    float (*bias_s)[64] = (float(*)[64])(smem + OFF_BIAS);
    float (*whr_s)[64]  = (float(*)[64])(smem + OFF_WHR);
    float4 (*red_s)[32] = (float4(*)[32])(smem + OFF_RED);

    const int tid  = threadIdx.x;
    const int wt   = tid >> 5;
    const int tg   = wt >> 1;           // t quarter (32 rows of 128)
    const int ng   = wt & 1;            // n half (32 cols of 64)
    const int lane = tid & 31;
    const int g5   = lane >> 2;
    const int tid4 = lane & 3;
    const int t0   = blockIdx.x * 128;
    const int n0   = blockIdx.y * 64;

    // ---- stage x tile (128 rows x 8 units) x {hi,lo}, swizzled ----
    {
        const uint4* sxh = (const uint4*)g_xh + (size_t)t0 * 8;
        const uint4* sxl = (const uint4*)g_xl + (size_t)t0 * 8;
#pragma unroll
        for (int it = 0; it < 4; it++) {
            const int i = tid + 256 * it;          // 0..1023
            const int r = i >> 3, u = i & 7;
            const int d = r * 8 + (u ^ (r & 7));
            ((uint4*)cxh)[d] = sxh[i];
            ((uint4*)cxl)[d] = sxl[i];
        }
    }
    // ---- stage W tiles (3 gates x 64 rows x 8 units) x {hi,lo}, swizzled ----
    {
#pragma unroll
        for (int it = 0; it < 6; it++) {
            const int i = tid + 256 * it;          // 0..1535
            const int s = i >> 9;
            const int rem = i & 511;
            const int n = rem >> 3, u = rem & 7;
            const size_t src = (size_t)(s * HH + n0 + n) * 8 + u;
            const int d = (s * 64 + n) * 8 + (u ^ (n & 7));
            ((uint4*)cwh)[d] = ((const uint4*)g_wh)[src];
            ((uint4*)cwl)[d] = ((const uint4*)g_wl)[src];
        }
    }
    if (tid < 64) {
        const int nn = n0 + tid;
        bias_s[0][tid] = bih[nn] + bhh[nn];
        bias_s[1][tid] = bih[2 * HH + nn] + bhh[2 * HH + nn];
        bias_s[2][tid] = bih[3 * HH + nn] + bhh[3 * HH + nn];
#pragma unroll
        for (int p = 0; p < 4; p++) whr_s[p][tid] = Whr[(size_t)p * HH + nn];
    }
    __syncthreads();

    // Accumulators: [t-set s][n-subtile j][gate][frag]
    float d[2][4][3][4];
#pragma unroll
    for (int s = 0; s < 2; s++)
#pragma unroll
        for (int j = 0; j < 4; j++)
#pragma unroll
            for (int g = 0; g < 3; g++)
#pragma unroll
                for (int e = 0; e < 4; e++) d[s][j][g][e] = 0.f;

#pragma unroll
    for (int ks = 0; ks < 4; ks++) {
        const int kb0 = ks * 32 + tid4 * 4;
        const int kb1 = kb0 + 16;

        uint32_t ah[2][4], al[2][4];
#pragma unroll
        for (int s = 0; s < 2; s++) {
            const int r0 = tg * 32 + s * 16 + g5;
            const int r1 = r0 + 8;
            const int x0 = (r0 & 7) << 4;
            const int x1 = (r1 & 7) << 4;
            ah[s][0] = *(const uint32_t*)(cxh + r0 * 128 + (kb0 ^ x0));
            ah[s][1] = *(const uint32_t*)(cxh + r1 * 128 + (kb0 ^ x1));
            ah[s][2] = *(const uint32_t*)(cxh + r0 * 128 + (kb1 ^ x0));
            ah[s][3] = *(const uint32_t*)(cxh + r1 * 128 + (kb1 ^ x1));
            al[s][0] = *(const uint32_t*)(cxl + r0 * 128 + (kb0 ^ x0));
            al[s][1] = *(const uint32_t*)(cxl + r1 * 128 + (kb0 ^ x1));
            al[s][2] = *(const uint32_t*)(cxl + r0 * 128 + (kb1 ^ x0));
            al[s][3] = *(const uint32_t*)(cxl + r1 * 128 + (kb1 ^ x1));
        }

#pragma unroll
        for (int g = 0; g < 3; g++) {
#pragma unroll
            for (int j = 0; j < 4; j++) {
                const int nrow = ng * 32 + j * 8 + g5;
                const int roff = (g * 64 + nrow) * 128;
                const int xrn = (nrow & 7) << 4;
                const uint32_t bh0 = *(const uint32_t*)(cwh + roff + (kb0 ^ xrn));
                const uint32_t bh1 = *(const uint32_t*)(cwh + roff + (kb1 ^ xrn));
                const uint32_t bl0 = *(const uint32_t*)(cwl + roff + (kb0 ^ xrn));
                const uint32_t bl1 = *(const uint32_t*)(cwl + roff + (kb1 ^ xrn));
#pragma unroll
                for (int s = 0; s < 2; s++) {
                    mma16816(d[s][j][g], ah[s][0], ah[s][1], ah[s][2], ah[s][3], bh0, bh1);
                    mma16816(d[s][j][g], ah[s][0], ah[s][1], ah[s][2], ah[s][3], bl0, bl1);
                    mma16816(d[s][j][g], al[s][0], al[s][1], al[s][2], al[s][3], bh0, bh1);
                }
            }
        }
    }

    // ---- epilogue: bias + LSTM cell + W_hr projection ----
    float hs[2][2][4];      // [s][row-half][p]
#pragma unroll
    for (int s = 0; s < 2; s++)
#pragma unroll
        for (int r = 0; r < 2; r++)
#pragma unroll
            for (int p = 0; p < 4; p++) hs[s][r][p] = 0.f;

#pragma unroll
    for (int s = 0; s < 2; s++) {
#pragma unroll
        for (int j = 0; j < 4; j++) {
#pragma unroll
            for (int e = 0; e < 4; e++) {
                const int rh = e >> 1, c = e & 1;
                const int nl = ng * 32 + j * 8 + tid4 * 2 + c;
                const float gi = d[s][j][0][e] + bias_s[0][nl];
                const float gg = d[s][j][1][e] + bias_s[1][nl];
                const float go = d[s][j][2][e] + bias_s[2][nl];
                const float cc = sig_fast(gi) * tanh_fast(gg);
                const float h  = sig_fast(go) * tanh_fast(cc);
#pragma unroll
                for (int p = 0; p < 4; p++)
                    hs[s][rh][p] = fmaf(h, whr_s[p][nl], hs[s][rh][p]);
            }
        }
    }

    // quad reduce -> per (t-row, warp) sum over its 32 n-cols
#pragma unroll
    for (int off = 1; off <= 2; off <<= 1)
#pragma unroll
        for (int s = 0; s < 2; s++)
#pragma unroll
            for (int r = 0; r < 2; r++)
#pragma unroll
                for (int p = 0; p < 4; p++)
                    hs[s][r][p] += __shfl_xor_sync(0xffffffffu, hs[s][r][p], off);

    // cross-ng fold in smem: ng=0 deposits, ng=1 adds and writes out
    if (ng == 0 && tid4 == 0) {
#pragma unroll
        for (int s = 0; s < 2; s++)
#pragma unroll
            for (int r = 0; r < 2; r++) {
                const int row = s * 16 + g5 + r * 8;     // 0..31
                red_s[tg][row] = make_float4(hs[s][r][0], hs[s][r][1],
                                             hs[s][r][2], hs[s][r][3]);
            }
    }
    __syncthreads();
    if (ng == 1 && tid4 == 0) {
#pragma unroll
        for (int s = 0; s < 2; s++)
#pragma unroll
            for (int r = 0; r < 2; r++) {
                const int row = s * 16 + g5 + r * 8;
                const float4 o = red_s[tg][row];
                const int tgl = t0 + tg * 32 + row;
                ((float4*)g_part)[(size_t)blockIdx.y * TT + tgl] =
                    make_float4(hs[s][r][0] + o.x, hs[s][r][1] + o.y,
                                hs[s][r][2] + o.z, hs[s][r][3] + o.w);
            }
    }
}

// Stage 1: fold 64 chunks -> 8. Grid (TT/256, 8), 256 thr. Coalesced.
__global__ __launch_bounds__(256)
void reduce_stage1()
{
    const int t  = blockIdx.x * 256 + threadIdx.x;
    const int cg = blockIdx.y;
    const float4* p = (const float4*)g_part;
    float4 s = make_float4(0.f, 0.f, 0.f, 0.f);
#pragma unroll
    for (int c = cg * 8; c < cg * 8 + 8; c++) {
        const float4 v = p[(size_t)c * TT + t];
        s.x += v.x; s.y += v.y; s.z += v.z; s.w += v.w;
    }
    ((float4*)g_p2)[(size_t)cg * TT + t] = s;
}

// ---------------------------------------------------------------------------
// Layers 1/2 (K=4): one thread = one timestep. Hidden split 8-way.
// Grid (TT/128, 8). Writes transposed partials [chunk][t].
// ---------------------------------------------------------------------------
__global__ __launch_bounds__(128)
void l12_gemm(int xsel,
              const float* __restrict__ Wih,
              const float* __restrict__ bih,
              const float* __restrict__ bhh,
              const float* __restrict__ Whr)
{
    const float* __restrict__ Y = g_ybuf[xsel];

    __shared__ float4 wsg[3][128];
    __shared__ float4 wrs[128];
    __shared__ float4 bss[128];

    const int tid = threadIdx.x;
    const int t   = blockIdx.x * 128 + tid;
    const int h0  = blockIdx.y * (HH / 8);

    const float4 y = ((const float4*)Y)[t];
    float a0 = 0.f, a1 = 0.f, a2 = 0.f, a3 = 0.f;

    const int gg[3] = {0, 2, 3};
    for (int tile = 0; tile < HH / 8; tile += 128) {
        __syncthreads();
        const int hr = h0 + tile + tid;
#pragma unroll
        for (int g = 0; g < 3; g++)
            wsg[g][tid] = ((const float4*)Wih)[gg[g] * HH + hr];
        {
            float4 wv;
            wv.x = Whr[0 * HH + hr];
            wv.y = Whr[1 * HH + hr];
            wv.z = Whr[2 * HH + hr];
            wv.w = Whr[3 * HH + hr];
            wrs[tid] = wv;
            float4 bv;
            bv.x = bih[hr] + bhh[hr];
            bv.y = bih[2 * HH + hr] + bhh[2 * HH + hr];
            bv.z = bih[3 * HH + hr] + bhh[3 * HH + hr];
            bv.w = 0.f;
            bss[tid] = bv;
        }
        __syncthreads();

#pragma unroll 4
        for (int r = 0; r < 128; r++) {
            const float4 wi = wsg[0][r];
            const float4 wg = wsg[1][r];
            const float4 wo = wsg[2][r];
            const float4 b  = bss[r];
            const float4 w  = wrs[r];
            float gi = b.x; dot4(gi, wi, y);
            float gv = b.y; dot4(gv, wg, y);
            float go = b.z; dot4(go, wo, y);
            const float c = sig_fast(gi) * tanh_fast(gv);
            const float h = sig_fast(go) * tanh_fast(c);
            a0 = fmaf(h, w.x, a0);
            a1 = fmaf(h, w.y, a1);
            a2 = fmaf(h, w.z, a2);
            a3 = fmaf(h, w.w, a3);
        }
    }

    ((float4*)g_part)[(size_t)blockIdx.y * TT + t] = make_float4(a0, a1, a2, a3);
}

// Final fold of NCH transposed chunks -> [T,4].  src: 0 = g_part, 1 = g_p2
template <int NCH>
__global__ void reduce_part_k(float* __restrict__ dext, int dsel, int ssel)
{
    float* dst = (dsel < 0) ? dext : g_ybuf[dsel];
    const float* src = ssel ? g_p2 : g_part;
    const int t = blockIdx.x * blockDim.x + threadIdx.x;
    if (t >= TT) return;
    const float4* p = (const float4*)src;
    float4 s = make_float4(0.f, 0.f, 0.f, 0.f);
#pragma unroll
    for (int c = 0; c < NCH; c++) {
        const float4 v = p[(size_t)c * TT + t];
        s.x += v.x; s.y += v.y; s.z += v.z; s.w += v.w;
    }
    ((float4*)dst)[t] = s;
}

extern "C" void kernel_launch(void* const* d_in, const int* in_sizes, int n_in,
                              void* d_out, int out_size)
{
    (void)in_sizes; (void)n_in; (void)out_size;

    const float* x    = (const float*)d_in[0];
    const float* Wih0 = (const float*)d_in[1];
    const float* bih0 = (const float*)d_in[3];
    const float* bhh0 = (const float*)d_in[4];
    const float* Whr0 = (const float*)d_in[5];
    const float* Wih1 = (const float*)d_in[6];
    const float* bih1 = (const float*)d_in[8];
    const float* bhh1 = (const float*)d_in[9];
    const float* Whr1 = (const float*)d_in[10];
    const float* Wih2 = (const float*)d_in[11];
    const float* bih2 = (const float*)d_in[13];
    const float* bhh2 = (const float*)d_in[14];
    const float* Whr2 = (const float*)d_in[15];
    float* out = (float*)d_out;

    // Unconditional (no static guards): host-side attribute set, not captured.
    cudaFuncSetAttribute(l0_mma, cudaFuncAttributeMaxDynamicSharedMemorySize, L0_SMEM);

    // Pre-convert to split-bf16
    conv_w2<<<384, 256>>>(Wih0);
    conv_x2<<<256, 256>>>(x);

    // Layer 0: tensor cores (mma.sync) + fused epilogue, two-stage reduce
    l0_mma<<<dim3(64, 64), 256, L0_SMEM>>>(bih0, bhh0, Whr0);
    reduce_stage1<<<dim3(TT / 256, 8), 256>>>();
    reduce_part_k<8><<<TT / 256, 256>>>(nullptr, 0, 1);

    // Layer 1
    l12_gemm<<<dim3(TT / 128, 8), 128>>>(0, Wih1, bih1, bhh1, Whr1);
    reduce_part_k<8><<<TT / 256, 256>>>(nullptr, 1, 0);
    // Layer 2
    l12_gemm<<<dim3(TT / 128, 8), 128>>>(1, Wih2, bih2, bhh2, Whr2);
    reduce_part_k<8><<<TT / 256, 256>>>(out, -1, 0);
}